// round 4
// baseline (speedup 1.0000x reference)
#include <cuda_runtime.h>
#include <cstdint>

// Problem constants (fixed shapes for this problem instance)
#define DD 128
#define TM 64            // nodes per combine tile
#define MAXN 100000

// Scratch (allocation-free rule: __device__ globals)
__device__ float g_agg[(size_t)MAXN * DD];
__device__ float g_h[(size_t)MAXN * DD];
__device__ float g_deg[MAXN];

typedef unsigned long long u64;

__device__ __forceinline__ u64 pk2(float v) {
    u64 r;
    asm("mov.b64 %0, {%1, %1};" : "=l"(r) : "f"(v));
    return r;
}
__device__ __forceinline__ void fma2(u64 &d, u64 a, u64 b) {
    asm("fma.rn.f32x2 %0, %1, %2, %0;" : "+l"(d) : "l"(a), "l"(b));
}
__device__ __forceinline__ float2 upk(u64 v) {
    float2 f;
    asm("mov.b64 {%0, %1}, %2;" : "=f"(f.x), "=f"(f.y) : "l"(v));
    return f;
}

// ---------------------------------------------------------------------------
// Degree: deg[dst] += 1 per edge
// ---------------------------------------------------------------------------
__global__ void deg_kernel(const int* __restrict__ ei, int E, float* __restrict__ deg) {
    int e = blockIdx.x * blockDim.x + threadIdx.x;
    if (e < E) atomicAdd(&deg[ei[E + e]], 1.0f);
}

// ---------------------------------------------------------------------------
// Scatter: agg[dst] += x[src] * rel[type]   (one warp per edge, float4 lanes)
// ---------------------------------------------------------------------------
__global__ void scatter_kernel(const float* __restrict__ x, const float* __restrict__ rel,
                               const int* __restrict__ ei, const int* __restrict__ et,
                               int E, float* __restrict__ agg) {
    int gw   = (blockIdx.x * blockDim.x + threadIdx.x) >> 5;
    int lane = threadIdx.x & 31;
    if (gw >= E) return;
    int src = __ldg(&ei[gw]);
    int dst = __ldg(&ei[E + gw]);
    int typ = __ldg(&et[gw]);
    float4 xv = *(const float4*)(x + (size_t)src * DD + lane * 4);
    float4 rv = __ldg((const float4*)(rel + (size_t)typ * DD + lane * 4));
    float4 m  = make_float4(xv.x * rv.x, xv.y * rv.y, xv.z * rv.z, xv.w * rv.w);
    atomicAdd((float4*)(agg + (size_t)dst * DD + lane * 4), m);  // RED.E.ADD.F32 vec4
}

// ---------------------------------------------------------------------------
// Jump: out[jdst] += jump_weight * edge_w * emb[jsrc]
// ---------------------------------------------------------------------------
__global__ void jump_kernel(const float* __restrict__ emb, const float* __restrict__ ew,
                            const int* __restrict__ ej, const float* __restrict__ jw,
                            int EJ, float* __restrict__ out) {
    int gw   = (blockIdx.x * blockDim.x + threadIdx.x) >> 5;
    int lane = threadIdx.x & 31;
    if (gw >= EJ) return;
    int src = __ldg(&ej[gw]);
    int dst = __ldg(&ej[EJ + gw]);
    float w = jw[0] * __ldg(&ew[gw]);
    float4 xv = *(const float4*)(emb + (size_t)src * DD + lane * 4);
    float4 m  = make_float4(w * xv.x, w * xv.y, w * xv.z, w * xv.w);
    atomicAdd((float4*)(out + (size_t)dst * DD + lane * 4), m);
}

// ---------------------------------------------------------------------------
// Combine: out[n] = x[n] + res * tanh( (agg[n]/max(deg,1)) @ W + x[n] @ Wl )
//   64-node tile / block, 256 threads, 192KB smem, FFMA2 (fma.rn.f32x2) core.
//   Thread (cg, rg): cols j0=cg*4 .. +3, rows r0=rg*8 .. +7, rows packed in pairs.
// ---------------------------------------------------------------------------
__global__ void __launch_bounds__(256, 1) combine_kernel(
    const float* __restrict__ agg, const float* __restrict__ deg,
    const float* __restrict__ x,   const float* __restrict__ W,
    const float* __restrict__ Wl,  const float* __restrict__ resp,
    float* __restrict__ out, int N)
{
    extern __shared__ float smem[];
    float* sW  = smem;                  // [k][j]  128*128
    float* sWl = sW + DD * DD;          // [k][j]  128*128
    float* sA  = sWl + DD * DD;         // [k][n]  128*64 (transposed, deg-scaled)
    float* sX  = sA + DD * TM;          // [k][n]  128*64 (transposed)

    int tid = threadIdx.x;
    int n0  = blockIdx.x * TM;

    // Load weight matrices (float4 vectorized)
    for (int i = tid; i < DD * DD / 4; i += 256) {
        ((float4*)sW)[i]  = ((const float4*)W)[i];
        ((float4*)sWl)[i] = ((const float4*)Wl)[i];
    }

    // Load A (scaled by 1/deg) and X transposed into smem
    int nn   = tid & (TM - 1);
    int kq   = tid >> 6;                 // 0..3 → k quarter
    int node = n0 + nn;
    bool valid = node < N;
    float sc = 1.0f;
    if (valid) sc = 1.0f / fmaxf(deg[node], 1.0f);
    for (int kk = kq * 32; kk < kq * 32 + 32; kk += 4) {
        float4 a  = valid ? *(const float4*)(agg + (size_t)node * DD + kk) : make_float4(0, 0, 0, 0);
        float4 xv = valid ? *(const float4*)(x   + (size_t)node * DD + kk) : make_float4(0, 0, 0, 0);
        sA[(kk + 0) * TM + nn] = a.x * sc;
        sA[(kk + 1) * TM + nn] = a.y * sc;
        sA[(kk + 2) * TM + nn] = a.z * sc;
        sA[(kk + 3) * TM + nn] = a.w * sc;
        sX[(kk + 0) * TM + nn] = xv.x;
        sX[(kk + 1) * TM + nn] = xv.y;
        sX[(kk + 2) * TM + nn] = xv.z;
        sX[(kk + 3) * TM + nn] = xv.w;
    }
    __syncthreads();

    int cg = tid & 31;
    int rg = tid >> 5;
    int j0 = cg * 4;
    int r0 = rg * 8;

    u64 acc[4][4];
    #pragma unroll
    for (int p = 0; p < 4; p++)
        #pragma unroll
        for (int c = 0; c < 4; c++) acc[p][c] = 0ULL;

    #pragma unroll 4
    for (int k = 0; k < DD; ++k) {
        float4 w  = *(const float4*)(sW  + k * DD + j0);
        float4 wl = *(const float4*)(sWl + k * DD + j0);
        u64 w2[4]  = {pk2(w.x),  pk2(w.y),  pk2(w.z),  pk2(w.w)};
        u64 wl2[4] = {pk2(wl.x), pk2(wl.y), pk2(wl.z), pk2(wl.w)};
        const u64* ap = (const u64*)(sA + k * TM + r0);   // row pairs, 8B aligned
        const u64* xp = (const u64*)(sX + k * TM + r0);
        u64 a2[4] = {ap[0], ap[1], ap[2], ap[3]};
        u64 x2[4] = {xp[0], xp[1], xp[2], xp[3]};
        #pragma unroll
        for (int p = 0; p < 4; p++) {
            #pragma unroll
            for (int c = 0; c < 4; c++) {
                fma2(acc[p][c], a2[p], w2[c]);
                fma2(acc[p][c], x2[p], wl2[c]);
            }
        }
    }

    float res = resp[0];
    #pragma unroll
    for (int p = 0; p < 4; p++) {
        float2 u0 = upk(acc[p][0]);
        float2 u1 = upk(acc[p][1]);
        float2 u2 = upk(acc[p][2]);
        float2 u3 = upk(acc[p][3]);
        int nlo = n0 + r0 + 2 * p;
        if (nlo < N) {
            float4 xo = *(const float4*)(x + (size_t)nlo * DD + j0);
            float4 o;
            o.x = xo.x + res * tanhf(u0.x);
            o.y = xo.y + res * tanhf(u1.x);
            o.z = xo.z + res * tanhf(u2.x);
            o.w = xo.w + res * tanhf(u3.x);
            *(float4*)(out + (size_t)nlo * DD + j0) = o;
        }
        int nhi = nlo + 1;
        if (nhi < N) {
            float4 xo = *(const float4*)(x + (size_t)nhi * DD + j0);
            float4 o;
            o.x = xo.x + res * tanhf(u0.y);
            o.y = xo.y + res * tanhf(u1.y);
            o.z = xo.z + res * tanhf(u2.y);
            o.w = xo.w + res * tanhf(u3.y);
            *(float4*)(out + (size_t)nhi * DD + j0) = o;
        }
    }
}

// ---------------------------------------------------------------------------
// Launch
// ---------------------------------------------------------------------------
extern "C" void kernel_launch(void* const* d_in, const int* in_sizes, int n_in,
                              void* d_out, int out_size) {
    const float* emb    = (const float*)d_in[0];
    const float* change = (const float*)d_in[1];
    const float* W1     = (const float*)d_in[2];
    const float* Wl1    = (const float*)d_in[3];
    const float* rel1   = (const float*)d_in[4];
    const float* W2     = (const float*)d_in[5];
    const float* Wl2    = (const float*)d_in[6];
    const float* rel2   = (const float*)d_in[7];
    const float* res    = (const float*)d_in[8];
    const float* jw     = (const float*)d_in[9];
    const float* ewj    = (const float*)d_in[10];
    const int*   ei     = (const int*)d_in[11];
    const int*   et     = (const int*)d_in[12];
    const int*   ej     = (const int*)d_in[13];

    int N  = in_sizes[0] / DD;       // 100000
    int E  = in_sizes[12];           // 600000
    int EJ = in_sizes[10];           // 300000

    float* out1 = (float*)d_out;
    float* out2 = out1 + (size_t)N * DD;

    float *agg, *h, *deg;
    cudaGetSymbolAddress((void**)&agg, g_agg);
    cudaGetSymbolAddress((void**)&h,   g_h);
    cudaGetSymbolAddress((void**)&deg, g_deg);

    const int SMEM_BYTES = (2 * DD * DD + 2 * DD * TM) * sizeof(float);  // 192 KB
    cudaFuncSetAttribute(combine_kernel, cudaFuncAttributeMaxDynamicSharedMemorySize, SMEM_BYTES);

    size_t fbytes = (size_t)N * DD * sizeof(float);
    int sblocks = (int)(((long long)E * 32 + 255) / 256);
    int jblocks = (int)(((long long)EJ * 32 + 255) / 256);
    int cblocks = (N + TM - 1) / TM;

    // Layer 1
    cudaMemsetAsync(agg, 0, fbytes, 0);
    cudaMemsetAsync(deg, 0, (size_t)N * sizeof(float), 0);
    deg_kernel<<<(E + 255) / 256, 256>>>(ei, E, deg);
    scatter_kernel<<<sblocks, 256>>>(emb, rel1, ei, et, E, agg);
    combine_kernel<<<cblocks, 256, SMEM_BYTES>>>(agg, deg, emb, W1, Wl1, res, h, N);

    // Layer 2 (writes h2 directly into out2)
    cudaMemsetAsync(agg, 0, fbytes, 0);
    scatter_kernel<<<sblocks, 256>>>(h, rel2, ei, et, E, agg);
    combine_kernel<<<cblocks, 256, SMEM_BYTES>>>(agg, deg, h, W2, Wl2, res, out2, N);

    // Jump diffusion accumulates into out2; change passthrough into out1
    jump_kernel<<<jblocks, 256>>>(emb, ewj, ej, jw, EJ, out2);
    cudaMemcpyAsync(out1, change, fbytes, cudaMemcpyDeviceToDevice, 0);
}

// round 9
// speedup vs baseline: 1.2632x; 1.2632x over previous
#include <cuda_runtime.h>
#include <cuda_bf16.h>
#include <cstdint>

#define DD 128
#define MAXN 100000
#define PK 136            // smem tile pitch in bf16 halves (conflict-free for ldmatrix)

// ---------------- scratch (__device__ globals; no allocs allowed) ----------------
__device__ float g_agg[(size_t)MAXN * DD];
__device__ float g_h[(size_t)MAXN * DD];
__device__ float g_deg[MAXN];
// bf16 hi/lo images of B = [W;Wloop]^T, row-major [n=128][k=256]:
// index l*2+0 = hi, l*2+1 = lo, per layer l.
__device__ __align__(16) __nv_bfloat16 g_B[4][32768];

__device__ __forceinline__ uint32_t smem_u32(const void* p) {
    uint32_t a;
    asm("{ .reg .u64 t; cvta.to.shared.u64 t, %1; cvt.u32.u64 %0, t; }" : "=r"(a) : "l"(p));
    return a;
}
__device__ __forceinline__ float tanh_fast(float v) {
    float r;
    asm("tanh.approx.f32 %0, %1;" : "=f"(r) : "f"(v));
    return r;
}
#define LDSM_X4(R, addr) \
    asm volatile("ldmatrix.sync.aligned.m8n8.x4.shared.b16 {%0,%1,%2,%3}, [%4];" \
        : "=r"((R)[0]), "=r"((R)[1]), "=r"((R)[2]), "=r"((R)[3]) : "r"(addr))

__device__ __forceinline__ void mma_bf16(float* c, const uint32_t* a, uint32_t b0, uint32_t b1) {
    asm volatile(
        "mma.sync.aligned.m16n8k16.row.col.f32.bf16.bf16.f32 "
        "{%0,%1,%2,%3}, {%4,%5,%6,%7}, {%8,%9}, {%0,%1,%2,%3};"
        : "+f"(c[0]), "+f"(c[1]), "+f"(c[2]), "+f"(c[3])
        : "r"(a[0]), "r"(a[1]), "r"(a[2]), "r"(a[3]), "r"(b0), "r"(b1));
}

// pack 4 floats -> 4 bf16 in a u64
__device__ __forceinline__ unsigned long long pk4(float a, float b, float c, float d) {
    unsigned long long r =  (unsigned long long)__bfloat16_as_ushort(__float2bfloat16(a));
    r |= (unsigned long long)__bfloat16_as_ushort(__float2bfloat16(b)) << 16;
    r |= (unsigned long long)__bfloat16_as_ushort(__float2bfloat16(c)) << 32;
    r |= (unsigned long long)__bfloat16_as_ushort(__float2bfloat16(d)) << 48;
    return r;
}

// ---------------------------------------------------------------------------
// Prep: B[n][k] = (k<128 ? W[k][n] : Wl[k-128][n]); hi/lo bf16 split, row-major.
// ---------------------------------------------------------------------------
__global__ void prep_kernel(const float* __restrict__ W1, const float* __restrict__ Wl1,
                            const float* __restrict__ W2, const float* __restrict__ Wl2) {
    int idx = blockIdx.x * blockDim.x + threadIdx.x;   // 0..65535
    int l = idx >> 15;
    int n = (idx >> 8) & 127;
    int k = idx & 255;
    const float* W  = l ? W2  : W1;
    const float* Wl = l ? Wl2 : Wl1;
    float v = (k < 128) ? W[k * 128 + n] : Wl[(k - 128) * 128 + n];
    __nv_bfloat16 hi = __float2bfloat16(v);
    __nv_bfloat16 lo = __float2bfloat16(v - __bfloat162float(hi));
    g_B[l * 2 + 0][n * 256 + k] = hi;
    g_B[l * 2 + 1][n * 256 + k] = lo;
}

// ---------------------------------------------------------------------------
// Scatter: agg[dst] += x[src] * rel[type]; 2 edges per warp (MLP), optional degree.
// ---------------------------------------------------------------------------
__global__ void scatter_kernel(const float* __restrict__ x, const float* __restrict__ rel,
                               const int* __restrict__ ei, const int* __restrict__ et,
                               int E, float* __restrict__ agg, float* __restrict__ deg) {
    int gw   = (blockIdx.x * blockDim.x + threadIdx.x) >> 5;
    int lane = threadIdx.x & 31;
    int e0 = gw * 2;
    if (e0 >= E) return;
    int e1 = e0 + 1;
    bool h1 = e1 < E;
    int s0 = __ldg(ei + e0), d0 = __ldg(ei + E + e0), t0 = __ldg(et + e0);
    int s1 = h1 ? __ldg(ei + e1) : 0, d1 = h1 ? __ldg(ei + E + e1) : 0,
        t1 = h1 ? __ldg(et + e1) : 0;
    float4 xa = *(const float4*)(x + (size_t)s0 * DD + lane * 4);
    float4 ra = __ldg((const float4*)(rel + (size_t)t0 * DD + lane * 4));
    float4 xb = make_float4(0, 0, 0, 0), rb = make_float4(0, 0, 0, 0);
    if (h1) {
        xb = *(const float4*)(x + (size_t)s1 * DD + lane * 4);
        rb = __ldg((const float4*)(rel + (size_t)t1 * DD + lane * 4));
    }
    float4 m0 = make_float4(xa.x * ra.x, xa.y * ra.y, xa.z * ra.z, xa.w * ra.w);
    atomicAdd((float4*)(agg + (size_t)d0 * DD + lane * 4), m0);
    if (h1) {
        float4 m1 = make_float4(xb.x * rb.x, xb.y * rb.y, xb.z * rb.z, xb.w * rb.w);
        atomicAdd((float4*)(agg + (size_t)d1 * DD + lane * 4), m1);
    }
    if (deg != nullptr && lane == 0) {
        atomicAdd(deg + d0, 1.0f);
        if (h1) atomicAdd(deg + d1, 1.0f);
    }
}

// ---------------------------------------------------------------------------
// Jump: out[jdst] += jump_weight * edge_w * emb[jsrc]; 2 edges per warp.
// ---------------------------------------------------------------------------
__global__ void jump_kernel(const float* __restrict__ emb, const float* __restrict__ ew,
                            const int* __restrict__ ej, const float* __restrict__ jw,
                            int EJ, float* __restrict__ out) {
    int gw   = (blockIdx.x * blockDim.x + threadIdx.x) >> 5;
    int lane = threadIdx.x & 31;
    int e0 = gw * 2;
    if (e0 >= EJ) return;
    int e1 = e0 + 1;
    bool h1 = e1 < EJ;
    float jwv = jw[0];
    int s0 = __ldg(ej + e0), d0 = __ldg(ej + EJ + e0);
    int s1 = h1 ? __ldg(ej + e1) : 0, d1 = h1 ? __ldg(ej + EJ + e1) : 0;
    float w0 = jwv * __ldg(ew + e0);
    float w1 = h1 ? jwv * __ldg(ew + e1) : 0.0f;
    float4 xa = *(const float4*)(emb + (size_t)s0 * DD + lane * 4);
    float4 xb = make_float4(0, 0, 0, 0);
    if (h1) xb = *(const float4*)(emb + (size_t)s1 * DD + lane * 4);
    float4 m0 = make_float4(w0 * xa.x, w0 * xa.y, w0 * xa.z, w0 * xa.w);
    atomicAdd((float4*)(out + (size_t)d0 * DD + lane * 4), m0);
    if (h1) {
        float4 m1 = make_float4(w1 * xb.x, w1 * xb.y, w1 * xb.z, w1 * xb.w);
        atomicAdd((float4*)(out + (size_t)d1 * DD + lane * 4), m1);
    }
}

// ---------------------------------------------------------------------------
// Combine (HMMA): out[n] = x[n] + res * tanh( [agg/deg | x] @ [W;Wl] )
// CTA: 128 nodes x 128 outs, K=256 in two 128-halves. 8 warps as 4(M) x 2(N).
// bf16 3-term split: Ah*Bh + Ah*Bl + Al*Bh in fp32 accumulators.
// smem: Ah, Al, Bh, Bl tiles of [128][PK=136] bf16 halves each.
// ---------------------------------------------------------------------------
__global__ void __launch_bounds__(256, 1) combine_hmma(
    const float* __restrict__ agg, const float* __restrict__ deg,
    const float* __restrict__ x,
    const __nv_bfloat16* __restrict__ Bhi, const __nv_bfloat16* __restrict__ Blo,
    const float* __restrict__ resp, float* __restrict__ out, int N)
{
    extern __shared__ char smem[];
    const int TILE = 128 * PK * 2;                 // 34816 B
    const int OF_AH = 0, OF_AL = TILE, OF_BH = 2 * TILE, OF_BL = 3 * TILE;
    const uint32_t sb = smem_u32(smem);

    int tid = threadIdx.x, wid = tid >> 5, lane = tid & 31;
    int n0 = blockIdx.x * 128;
    int wm = wid & 3, wn = wid >> 2;

    // lane-pattern for ldmatrix x4: row += (lane&7) + ((lane>>3)&1)*8, col += ((lane>>4)&1)*8
    int lrow = (lane & 7) + ((lane >> 3) & 1) * 8;
    int lcol = ((lane >> 4) & 1) * 8;

    // Per-warp ldmatrix base byte-offsets (k advances by 32B per k16-step)
    uint32_t aoffs[2], boffs[4];
    #pragma unroll
    for (int mi = 0; mi < 2; mi++)
        aoffs[mi] = (uint32_t)(((wm * 32 + mi * 16 + lrow) * PK + lcol) * 2);
    #pragma unroll
    for (int bj = 0; bj < 4; bj++)
        boffs[bj] = (uint32_t)(((wn * 64 + bj * 16 + lrow) * PK + lcol) * 2);

    float acc[2][8][4];
    #pragma unroll
    for (int mi = 0; mi < 2; mi++)
        #pragma unroll
        for (int j = 0; j < 8; j++)
            #pragma unroll
            for (int q = 0; q < 4; q++) acc[mi][j][q] = 0.0f;

    for (int half = 0; half < 2; half++) {
        if (half) __syncthreads();                 // everyone done with smem

        // --- load A half: rows = nodes, cols = 128 K-slice (agg/deg or x)
        const float* src = half ? x : agg;
        for (int i = tid; i < 128 * 32; i += 256) {
            int row = i >> 5, c4 = i & 31, node = n0 + row;
            float4 v = make_float4(0, 0, 0, 0);
            if (node < N) {
                v = ((const float4*)(src + (size_t)node * DD))[c4];
                if (half == 0) {
                    float sc = 1.0f / fmaxf(deg[node], 1.0f);
                    v.x *= sc; v.y *= sc; v.z *= sc; v.w *= sc;
                }
            }
            __nv_bfloat16 h0 = __float2bfloat16(v.x), h1b = __float2bfloat16(v.y);
            __nv_bfloat16 h2 = __float2bfloat16(v.z), h3 = __float2bfloat16(v.w);
            float l0 = v.x - __bfloat162float(h0), l1 = v.y - __bfloat162float(h1b);
            float l2 = v.z - __bfloat162float(h2), l3 = v.w - __bfloat162float(h3);
            size_t doff = (size_t)(row * PK + c4 * 4) * 2;
            unsigned long long hp =
                (unsigned long long)__bfloat16_as_ushort(h0) |
                ((unsigned long long)__bfloat16_as_ushort(h1b) << 16) |
                ((unsigned long long)__bfloat16_as_ushort(h2) << 32) |
                ((unsigned long long)__bfloat16_as_ushort(h3) << 48);
            *(unsigned long long*)(smem + OF_AH + doff) = hp;
            *(unsigned long long*)(smem + OF_AL + doff) = pk4(l0, l1, l2, l3);
        }
        // --- load B half: [n][k-slice] from prebuilt images
        const uint4* bh = (const uint4*)(Bhi + half * 128);
        const uint4* bl = (const uint4*)(Blo + half * 128);
        for (int i = tid; i < 128 * 16; i += 256) {
            int row = i >> 4, c = i & 15;                 // c*8 halves within 128-slice
            uint4 vh = bh[(row * 256) / 8 + c];
            uint4 vl = bl[(row * 256) / 8 + c];
            size_t doff = (size_t)row * PK * 2 + (size_t)c * 16;
            *(uint4*)(smem + OF_BH + doff) = vh;
            *(uint4*)(smem + OF_BL + doff) = vl;
        }
        __syncthreads();

        // --- MMA over 8 k16 steps
        #pragma unroll
        for (int s = 0; s < 8; s++) {
            uint32_t kb = (uint32_t)s * 32;
            uint32_t ah[2][4], al[2][4];
            #pragma unroll
            for (int mi = 0; mi < 2; mi++) {
                LDSM_X4(ah[mi], sb + OF_AH + aoffs[mi] + kb);
                LDSM_X4(al[mi], sb + OF_AL + aoffs[mi] + kb);
            }
            #pragma unroll
            for (int bj = 0; bj < 4; bj++) {
                uint32_t bhf[4], blf[4];
                LDSM_X4(bhf, sb + OF_BH + boffs[bj] + kb);
                LDSM_X4(blf, sb + OF_BL + boffs[bj] + kb);
                #pragma unroll
                for (int mi = 0; mi < 2; mi++) {
                    // n8 tile t0 = bj*2 : b regs {r0, r2};  t1 = bj*2+1 : {r1, r3}
                    mma_bf16(acc[mi][bj * 2 + 0], ah[mi], bhf[0], bhf[2]);
                    mma_bf16(acc[mi][bj * 2 + 0], ah[mi], blf[0], blf[2]);
                    mma_bf16(acc[mi][bj * 2 + 0], al[mi], bhf[0], bhf[2]);
                    mma_bf16(acc[mi][bj * 2 + 1], ah[mi], bhf[1], bhf[3]);
                    mma_bf16(acc[mi][bj * 2 + 1], ah[mi], blf[1], blf[3]);
                    mma_bf16(acc[mi][bj * 2 + 1], al[mi], bhf[1], bhf[3]);
                }
            }
        }
    }

    // --- epilogue: C frag thread t holds rows (t>>2)+{0,8}, cols 2*(t&3)+{0,1}
    float res = resp[0];
    int rbase = n0 + wm * 32 + (lane >> 2);
    int cbase = wn * 64 + (lane & 3) * 2;
    #pragma unroll
    for (int mi = 0; mi < 2; mi++) {
        #pragma unroll
        for (int j = 0; j < 8; j++) {
            int col = cbase + j * 8;
            int nlo = rbase + mi * 16;
            int nhi = nlo + 8;
            if (nlo < N) {
                const float2 xv = *(const float2*)(x + (size_t)nlo * DD + col);
                float2 o;
                o.x = xv.x + res * tanh_fast(acc[mi][j][0]);
                o.y = xv.y + res * tanh_fast(acc[mi][j][1]);
                *(float2*)(out + (size_t)nlo * DD + col) = o;
            }
            if (nhi < N) {
                const float2 xv = *(const float2*)(x + (size_t)nhi * DD + col);
                float2 o;
                o.x = xv.x + res * tanh_fast(acc[mi][j][2]);
                o.y = xv.y + res * tanh_fast(acc[mi][j][3]);
                *(float2*)(out + (size_t)nhi * DD + col) = o;
            }
        }
    }
}

// ---------------------------------------------------------------------------
// Launch
// ---------------------------------------------------------------------------
extern "C" void kernel_launch(void* const* d_in, const int* in_sizes, int n_in,
                              void* d_out, int out_size) {
    const float* emb    = (const float*)d_in[0];
    const float* change = (const float*)d_in[1];
    const float* W1     = (const float*)d_in[2];
    const float* Wl1    = (const float*)d_in[3];
    const float* rel1   = (const float*)d_in[4];
    const float* W2     = (const float*)d_in[5];
    const float* Wl2    = (const float*)d_in[6];
    const float* rel2   = (const float*)d_in[7];
    const float* res    = (const float*)d_in[8];
    const float* jw     = (const float*)d_in[9];
    const float* ewj    = (const float*)d_in[10];
    const int*   ei     = (const int*)d_in[11];
    const int*   et     = (const int*)d_in[12];
    const int*   ej     = (const int*)d_in[13];

    int N  = in_sizes[0] / DD;       // 100000
    int E  = in_sizes[12];           // 600000
    int EJ = in_sizes[10];           // 300000

    float* out1 = (float*)d_out;
    float* out2 = out1 + (size_t)N * DD;

    float *agg, *h, *deg;
    __nv_bfloat16 (*B)[32768];
    cudaGetSymbolAddress((void**)&agg, g_agg);
    cudaGetSymbolAddress((void**)&h,   g_h);
    cudaGetSymbolAddress((void**)&deg, g_deg);
    cudaGetSymbolAddress((void**)&B,   g_B);

    const int SMEM_C = 4 * 128 * PK * 2;   // 139264 B
    cudaFuncSetAttribute(combine_hmma, cudaFuncAttributeMaxDynamicSharedMemorySize, SMEM_C);

    size_t fbytes = (size_t)N * DD * sizeof(float);
    long long swarps = (E + 1) / 2;
    long long jwarps = (EJ + 1) / 2;
    int sblocks = (int)((swarps * 32 + 255) / 256);
    int jblocks = (int)((jwarps * 32 + 255) / 256);
    int cblocks = (N + 127) / 128;

    prep_kernel<<<256, 256>>>(W1, Wl1, W2, Wl2);
    cudaMemsetAsync(agg, 0, fbytes, 0);
    cudaMemsetAsync(deg, 0, (size_t)N * sizeof(float), 0);

    // Layer 1 (degree fused into scatter)
    scatter_kernel<<<sblocks, 256>>>(emb, rel1, ei, et, E, agg, deg);
    combine_hmma<<<cblocks, 256, SMEM_C>>>(agg, deg, emb, B[0], B[1], res, h, N);

    // Layer 2 (writes directly into out2)
    cudaMemsetAsync(agg, 0, fbytes, 0);
    scatter_kernel<<<sblocks, 256>>>(h, rel2, ei, et, E, agg, nullptr);
    combine_hmma<<<cblocks, 256, SMEM_C>>>(agg, deg, h, B[2], B[3], res, out2, N);

    // Jump diffusion accumulates into out2; change passthrough into out1
    jump_kernel<<<jblocks, 256>>>(emb, ewj, ej, jw, EJ, out2);
    cudaMemcpyAsync(out1, change, fbytes, cudaMemcpyDeviceToDevice, 0);
}

// round 13
// speedup vs baseline: 1.5907x; 1.2593x over previous
#include <cuda_runtime.h>
#include <cuda_bf16.h>
#include <cstdint>

#define DD 128
#define MAXN 100000
#define PK 136            // smem tile pitch in bf16 halves (conflict-free for ldmatrix)

// ---------------- scratch (__device__ globals; no allocs allowed) ----------------
__device__ float g_agg[(size_t)MAXN * DD];
__device__ float g_h[(size_t)MAXN * DD];
__device__ float g_deg[MAXN];
// bf16 hi/lo images of B = [W;Wloop]^T, row-major [n=128][k=256]:
// index l*2+0 = hi, l*2+1 = lo, per layer l.
__device__ __align__(16) __nv_bfloat16 g_B[4][32768];

__device__ __forceinline__ uint32_t smem_u32(const void* p) {
    uint32_t a;
    asm("{ .reg .u64 t; cvta.to.shared.u64 t, %1; cvt.u32.u64 %0, t; }" : "=r"(a) : "l"(p));
    return a;
}
__device__ __forceinline__ float tanh_fast(float v) {
    float r;
    asm("tanh.approx.f32 %0, %1;" : "=f"(r) : "f"(v));
    return r;
}
#define LDSM_X4(R, addr) \
    asm volatile("ldmatrix.sync.aligned.m8n8.x4.shared.b16 {%0,%1,%2,%3}, [%4];" \
        : "=r"((R)[0]), "=r"((R)[1]), "=r"((R)[2]), "=r"((R)[3]) : "r"(addr))

__device__ __forceinline__ void mma_bf16(float* c, const uint32_t* a, uint32_t b0, uint32_t b1) {
    asm volatile(
        "mma.sync.aligned.m16n8k16.row.col.f32.bf16.bf16.f32 "
        "{%0,%1,%2,%3}, {%4,%5,%6,%7}, {%8,%9}, {%0,%1,%2,%3};"
        : "+f"(c[0]), "+f"(c[1]), "+f"(c[2]), "+f"(c[3])
        : "r"(a[0]), "r"(a[1]), "r"(a[2]), "r"(a[3]), "r"(b0), "r"(b1));
}

// pack 4 floats -> 4 bf16 in a u64
__device__ __forceinline__ unsigned long long pk4(float a, float b, float c, float d) {
    unsigned long long r =  (unsigned long long)__bfloat16_as_ushort(__float2bfloat16(a));
    r |= (unsigned long long)__bfloat16_as_ushort(__float2bfloat16(b)) << 16;
    r |= (unsigned long long)__bfloat16_as_ushort(__float2bfloat16(c)) << 32;
    r |= (unsigned long long)__bfloat16_as_ushort(__float2bfloat16(d)) << 48;
    return r;
}

// ---------------------------------------------------------------------------
// Prep: B[n][k] = (k<128 ? W[k][n] : Wl[k-128][n]); hi/lo bf16 split, row-major.
// ---------------------------------------------------------------------------
__global__ void prep_kernel(const float* __restrict__ W1, const float* __restrict__ Wl1,
                            const float* __restrict__ W2, const float* __restrict__ Wl2) {
    int idx = blockIdx.x * blockDim.x + threadIdx.x;   // 0..65535
    int l = idx >> 15;
    int n = (idx >> 8) & 127;
    int k = idx & 255;
    const float* W  = l ? W2  : W1;
    const float* Wl = l ? Wl2 : Wl1;
    float v = (k < 128) ? W[k * 128 + n] : Wl[(k - 128) * 128 + n];
    __nv_bfloat16 hi = __float2bfloat16(v);
    __nv_bfloat16 lo = __float2bfloat16(v - __bfloat162float(hi));
    g_B[l * 2 + 0][n * 256 + k] = hi;
    g_B[l * 2 + 1][n * 256 + k] = lo;
}

// ---------------------------------------------------------------------------
// Scatter: agg[dst] += x[src] * rel[type]; 4 edges per warp (MLP), optional degree.
// ---------------------------------------------------------------------------
__global__ void scatter_kernel(const float* __restrict__ x, const float* __restrict__ rel,
                               const int* __restrict__ ei, const int* __restrict__ et,
                               int E, float* __restrict__ agg, float* __restrict__ deg) {
    int gw   = (blockIdx.x * blockDim.x + threadIdx.x) >> 5;
    int lane = threadIdx.x & 31;
    int e0 = gw * 4;
    if (e0 >= E) return;
    int   sidx[4], didx[4], tidx[4];
    bool  ok[4];
    #pragma unroll
    for (int q = 0; q < 4; q++) {
        int e = e0 + q;
        ok[q] = e < E;
        int es = ok[q] ? e : e0;
        sidx[q] = __ldg(ei + es);
        didx[q] = __ldg(ei + E + es);
        tidx[q] = __ldg(et + es);
    }
    float4 xv[4], rv[4];
    #pragma unroll
    for (int q = 0; q < 4; q++) {
        xv[q] = *(const float4*)(x + (size_t)sidx[q] * DD + lane * 4);
        rv[q] = __ldg((const float4*)(rel + (size_t)tidx[q] * DD + lane * 4));
    }
    #pragma unroll
    for (int q = 0; q < 4; q++) {
        if (ok[q]) {
            float4 m = make_float4(xv[q].x * rv[q].x, xv[q].y * rv[q].y,
                                   xv[q].z * rv[q].z, xv[q].w * rv[q].w);
            atomicAdd((float4*)(agg + (size_t)didx[q] * DD + lane * 4), m);
        }
    }
    if (deg != nullptr && lane == 0) {
        #pragma unroll
        for (int q = 0; q < 4; q++)
            if (ok[q]) atomicAdd(deg + didx[q], 1.0f);
    }
}

// ---------------------------------------------------------------------------
// Jump: out[jdst] += jump_weight * edge_w * emb[jsrc]; 4 edges per warp.
// ---------------------------------------------------------------------------
__global__ void jump_kernel(const float* __restrict__ emb, const float* __restrict__ ew,
                            const int* __restrict__ ej, const float* __restrict__ jw,
                            int EJ, float* __restrict__ out) {
    int gw   = (blockIdx.x * blockDim.x + threadIdx.x) >> 5;
    int lane = threadIdx.x & 31;
    int e0 = gw * 4;
    if (e0 >= EJ) return;
    float jwv = jw[0];
    int  sidx[4], didx[4];
    bool ok[4];
    float wq[4];
    #pragma unroll
    for (int q = 0; q < 4; q++) {
        int e = e0 + q;
        ok[q] = e < EJ;
        int es = ok[q] ? e : e0;
        sidx[q] = __ldg(ej + es);
        didx[q] = __ldg(ej + EJ + es);
        wq[q]   = jwv * __ldg(ew + es);
    }
    float4 xv[4];
    #pragma unroll
    for (int q = 0; q < 4; q++)
        xv[q] = *(const float4*)(emb + (size_t)sidx[q] * DD + lane * 4);
    #pragma unroll
    for (int q = 0; q < 4; q++) {
        if (ok[q]) {
            float4 m = make_float4(wq[q] * xv[q].x, wq[q] * xv[q].y,
                                   wq[q] * xv[q].z, wq[q] * xv[q].w);
            atomicAdd((float4*)(out + (size_t)didx[q] * DD + lane * 4), m);
        }
    }
}

// ---------------------------------------------------------------------------
// Combine (HMMA): out[n] = x[n] + res * tanh( [agg/deg | x] @ [W;Wl] )
// CTA: 64 nodes x 128 outs, K=256 in two 128-halves. 8 warps as 2(M) x 4(N).
// 104.5KB smem -> 2 CTAs/SM for cross-CTA phase overlap.
// bf16 3-term split: Ah*Bh + Ah*Bl + Al*Bh in fp32 accumulators.
// ---------------------------------------------------------------------------
__global__ void __launch_bounds__(256, 2) combine_hmma(
    const float* __restrict__ agg, const float* __restrict__ deg,
    const float* __restrict__ x,
    const __nv_bfloat16* __restrict__ Bhi, const __nv_bfloat16* __restrict__ Blo,
    const float* __restrict__ resp, float* __restrict__ out, int N)
{
    extern __shared__ char smem[];
    const int TILE_A = 64 * PK * 2;                  // 17408 B
    const int TILE_B = 128 * PK * 2;                 // 34816 B
    const int OF_AH = 0, OF_AL = TILE_A, OF_BH = 2 * TILE_A, OF_BL = 2 * TILE_A + TILE_B;
    const uint32_t sb = smem_u32(smem);

    int tid = threadIdx.x, wid = tid >> 5, lane = tid & 31;
    int n0 = blockIdx.x * 64;
    int wn = wid & 3, wm = wid >> 2;                 // 4 N-groups x 2 M-groups

    int lrow = (lane & 7) + ((lane >> 3) & 1) * 8;
    int lcol = ((lane >> 4) & 1) * 8;

    uint32_t aoffs[2], boffs[2];
    #pragma unroll
    for (int mi = 0; mi < 2; mi++)
        aoffs[mi] = (uint32_t)(((wm * 32 + mi * 16 + lrow) * PK + lcol) * 2);
    #pragma unroll
    for (int bj = 0; bj < 2; bj++)
        boffs[bj] = (uint32_t)(((wn * 32 + bj * 16 + lrow) * PK + lcol) * 2);

    float acc[2][4][4];
    #pragma unroll
    for (int mi = 0; mi < 2; mi++)
        #pragma unroll
        for (int j = 0; j < 4; j++)
            #pragma unroll
            for (int q = 0; q < 4; q++) acc[mi][j][q] = 0.0f;

    for (int half = 0; half < 2; half++) {
        if (half) __syncthreads();

        // --- A half: 64 rows x 128-k slice (agg/deg or x), hi/lo split
        const float* src = half ? x : agg;
        for (int i = tid; i < 64 * 32; i += 256) {
            int row = i >> 5, c4 = i & 31, node = n0 + row;
            float4 v = make_float4(0, 0, 0, 0);
            if (node < N) {
                v = ((const float4*)(src + (size_t)node * DD))[c4];
                if (half == 0) {
                    float sc = 1.0f / fmaxf(deg[node], 1.0f);
                    v.x *= sc; v.y *= sc; v.z *= sc; v.w *= sc;
                }
            }
            __nv_bfloat16 h0 = __float2bfloat16(v.x), h1b = __float2bfloat16(v.y);
            __nv_bfloat16 h2 = __float2bfloat16(v.z), h3 = __float2bfloat16(v.w);
            float l0 = v.x - __bfloat162float(h0), l1 = v.y - __bfloat162float(h1b);
            float l2 = v.z - __bfloat162float(h2), l3 = v.w - __bfloat162float(h3);
            size_t doff = (size_t)(row * PK + c4 * 4) * 2;
            unsigned long long hp =
                (unsigned long long)__bfloat16_as_ushort(h0) |
                ((unsigned long long)__bfloat16_as_ushort(h1b) << 16) |
                ((unsigned long long)__bfloat16_as_ushort(h2) << 32) |
                ((unsigned long long)__bfloat16_as_ushort(h3) << 48);
            *(unsigned long long*)(smem + OF_AH + doff) = hp;
            *(unsigned long long*)(smem + OF_AL + doff) = pk4(l0, l1, l2, l3);
        }
        // --- B half: [128 n][128 k-slice] from prebuilt images (pure copy)
        const uint4* bh = (const uint4*)(Bhi + half * 128);
        const uint4* bl = (const uint4*)(Blo + half * 128);
        for (int i = tid; i < 128 * 16; i += 256) {
            int row = i >> 4, c = i & 15;
            uint4 vh = bh[row * 32 + c];
            uint4 vl = bl[row * 32 + c];
            size_t doff = (size_t)row * PK * 2 + (size_t)c * 16;
            *(uint4*)(smem + OF_BH + doff) = vh;
            *(uint4*)(smem + OF_BL + doff) = vl;
        }
        __syncthreads();

        // --- MMA over 8 k16 steps
        #pragma unroll
        for (int s = 0; s < 8; s++) {
            uint32_t kb = (uint32_t)s * 32;
            uint32_t ah[2][4], al[2][4];
            #pragma unroll
            for (int mi = 0; mi < 2; mi++) {
                LDSM_X4(ah[mi], sb + OF_AH + aoffs[mi] + kb);
                LDSM_X4(al[mi], sb + OF_AL + aoffs[mi] + kb);
            }
            #pragma unroll
            for (int bj = 0; bj < 2; bj++) {
                uint32_t bhf[4], blf[4];
                LDSM_X4(bhf, sb + OF_BH + boffs[bj] + kb);
                LDSM_X4(blf, sb + OF_BL + boffs[bj] + kb);
                #pragma unroll
                for (int mi = 0; mi < 2; mi++) {
                    mma_bf16(acc[mi][bj * 2 + 0], ah[mi], bhf[0], bhf[2]);
                    mma_bf16(acc[mi][bj * 2 + 0], ah[mi], blf[0], blf[2]);
                    mma_bf16(acc[mi][bj * 2 + 0], al[mi], bhf[0], bhf[2]);
                    mma_bf16(acc[mi][bj * 2 + 1], ah[mi], bhf[1], bhf[3]);
                    mma_bf16(acc[mi][bj * 2 + 1], ah[mi], blf[1], blf[3]);
                    mma_bf16(acc[mi][bj * 2 + 1], al[mi], bhf[1], bhf[3]);
                }
            }
        }
    }

    // --- epilogue: warp covers rows wm*32..+31, cols wn*32..+31
    float res = resp[0];
    int rbase = n0 + wm * 32 + (lane >> 2);
    int cbase = wn * 32 + (lane & 3) * 2;
    #pragma unroll
    for (int mi = 0; mi < 2; mi++) {
        #pragma unroll
        for (int j = 0; j < 4; j++) {
            int col = cbase + j * 8;
            int nlo = rbase + mi * 16;
            int nhi = nlo + 8;
            if (nlo < N) {
                const float2 xv = *(const float2*)(x + (size_t)nlo * DD + col);
                float2 o;
                o.x = xv.x + res * tanh_fast(acc[mi][j][0]);
                o.y = xv.y + res * tanh_fast(acc[mi][j][1]);
                *(float2*)(out + (size_t)nlo * DD + col) = o;
            }
            if (nhi < N) {
                const float2 xv = *(const float2*)(x + (size_t)nhi * DD + col);
                float2 o;
                o.x = xv.x + res * tanh_fast(acc[mi][j][2]);
                o.y = xv.y + res * tanh_fast(acc[mi][j][3]);
                *(float2*)(out + (size_t)nhi * DD + col) = o;
            }
        }
    }
}

// ---------------------------------------------------------------------------
// Launch
// ---------------------------------------------------------------------------
extern "C" void kernel_launch(void* const* d_in, const int* in_sizes, int n_in,
                              void* d_out, int out_size) {
    const float* emb    = (const float*)d_in[0];
    const float* change = (const float*)d_in[1];
    const float* W1     = (const float*)d_in[2];
    const float* Wl1    = (const float*)d_in[3];
    const float* rel1   = (const float*)d_in[4];
    const float* W2     = (const float*)d_in[5];
    const float* Wl2    = (const float*)d_in[6];
    const float* rel2   = (const float*)d_in[7];
    const float* res    = (const float*)d_in[8];
    const float* jw     = (const float*)d_in[9];
    const float* ewj    = (const float*)d_in[10];
    const int*   ei     = (const int*)d_in[11];
    const int*   et     = (const int*)d_in[12];
    const int*   ej     = (const int*)d_in[13];

    int N  = in_sizes[0] / DD;       // 100000
    int E  = in_sizes[12];           // 600000
    int EJ = in_sizes[10];           // 300000

    float* out1 = (float*)d_out;
    float* out2 = out1 + (size_t)N * DD;

    float *agg, *h, *deg;
    __nv_bfloat16 (*B)[32768];
    cudaGetSymbolAddress((void**)&agg, g_agg);
    cudaGetSymbolAddress((void**)&h,   g_h);
    cudaGetSymbolAddress((void**)&deg, g_deg);
    cudaGetSymbolAddress((void**)&B,   g_B);

    const int SMEM_C = 2 * 64 * PK * 2 + 2 * 128 * PK * 2;   // 104448 B
    cudaFuncSetAttribute(combine_hmma, cudaFuncAttributeMaxDynamicSharedMemorySize, SMEM_C);

    size_t fbytes = (size_t)N * DD * sizeof(float);
    long long swarps = (E + 3) / 4;
    long long jwarps = (EJ + 3) / 4;
    int sblocks = (int)((swarps * 32 + 255) / 256);
    int jblocks = (int)((jwarps * 32 + 255) / 256);
    int cblocks = (N + 63) / 64;

    prep_kernel<<<256, 256>>>(W1, Wl1, W2, Wl2);
    cudaMemsetAsync(agg, 0, fbytes, 0);
    cudaMemsetAsync(deg, 0, (size_t)N * sizeof(float), 0);

    // Layer 1 (degree fused into scatter)
    scatter_kernel<<<sblocks, 256>>>(emb, rel1, ei, et, E, agg, deg);
    combine_hmma<<<cblocks, 256, SMEM_C>>>(agg, deg, emb, B[0], B[1], res, h, N);

    // Layer 2 (writes directly into out2)
    cudaMemsetAsync(agg, 0, fbytes, 0);
    scatter_kernel<<<sblocks, 256>>>(h, rel2, ei, et, E, agg, nullptr);
    combine_hmma<<<cblocks, 256, SMEM_C>>>(agg, deg, h, B[2], B[3], res, out2, N);

    // Jump diffusion accumulates into out2; change passthrough into out1
    jump_kernel<<<jblocks, 256>>>(emb, ewj, ej, jw, EJ, out2);
    cudaMemcpyAsync(out1, change, fbytes, cudaMemcpyDeviceToDevice, 0);
}